// round 1
// baseline (speedup 1.0000x reference)
#include <cuda_runtime.h>
#include <cuda_bf16.h>

// Problem dims (fixed by the dataset)
#define LSEQ 512
#define DIN  320
#define HID  512
#define G4   2048   // 4*H
#define MDIM 512

// ---------------- scratch (static device globals; no allocation) ----------
__device__ float g_x0 [LSEQ * DIN];        // embeddings
__device__ float g_x1 [LSEQ * 2 * HID];    // layer0 output (fwd cols 0..511, bwd 512..1023)
__device__ float g_x2 [LSEQ * 2 * HID];    // layer1 output
__device__ float g_zf [LSEQ * G4];         // input-projection, forward dir
__device__ float g_zb [LSEQ * G4];         // input-projection, backward dir
__device__ float g_mlp[LSEQ * MDIM];       // per-node MLP
__device__ unsigned int g_cnt[2 * LSEQ];   // per-step publish counters (layer0: [0,1024), layer1: [1024,2048))

__device__ __forceinline__ float* bufsel(int id) {
    switch (id) {
        case 0: return g_x0;
        case 1: return g_x1;
        case 2: return g_x2;
        case 3: return g_zf;
        case 4: return g_zb;
        default: return g_mlp;
    }
}

__device__ __forceinline__ float sigm_f(float x) {
    float e = __expf(-x);            // 2-ulp; saturates correctly at +-inf
    return 1.0f / (1.0f + e);
}
__device__ __forceinline__ float tanh_f(float x) {
    float a = fabsf(x);
    float e = __expf(-2.0f * a);     // e in (0,1], no overflow
    float r = (1.0f - e) / (1.0f + e);
    return copysignf(r, x);
}

// ---------------- embedding gather ----------------------------------------
__global__ void embed_k(const int* __restrict__ wi, const int* __restrict__ pi,
                        const float* __restrict__ we, const float* __restrict__ pe)
{
    int t = blockIdx.x;
    int d = threadIdx.x;             // 320 threads
    float v;
    if (d < 256) v = we[(size_t)wi[t] * 256 + d];
    else         v = pe[(size_t)pi[t] * 64 + (d - 256)];
    g_x0[t * DIN + d] = v;
}

// ---------------- counter reset (needed every replay) ---------------------
__global__ void zero_k()
{
    g_cnt[blockIdx.x * 1024 + threadIdx.x] = 0u;
}

// ---------------- f32 GEMM:  C[M,N] = A[M,K] * B[N,K]^T + b1 + b2 ---------
// 64x64 block tile, 256 threads, 4x4 per thread, K-tile 16.
// All shapes here are multiples of the tiles (M=512, N in {2048,512}, K in {320,1024}).
__global__ void __launch_bounds__(256) gemm_tn(
    int aid, const float* __restrict__ B,
    const float* __restrict__ b1, const float* __restrict__ b2,
    int cid, int M, int N, int K)
{
    const float* A = bufsel(aid);
    float*       C = bufsel(cid);

    __shared__ float As[16][65];
    __shared__ float Bs[16][65];

    const int tid = threadIdx.x;
    const int tx  = tid & 15;
    const int ty  = tid >> 4;
    const int m0  = blockIdx.y * 64;
    const int n0  = blockIdx.x * 64;

    const int lr = tid >> 2;         // 0..63 : tile row
    const int lk = (tid & 3) * 4;    // 0,4,8,12 : k offset (float4)

    const float* Ap = A + (size_t)(m0 + lr) * K + lk;
    const float* Bp = B + (size_t)(n0 + lr) * K + lk;

    float acc[4][4] = {};

    for (int k0 = 0; k0 < K; k0 += 16) {
        float4 av = *(const float4*)(Ap + k0);
        float4 bv = *(const float4*)(Bp + k0);
        __syncthreads();
        As[lk + 0][lr] = av.x; As[lk + 1][lr] = av.y;
        As[lk + 2][lr] = av.z; As[lk + 3][lr] = av.w;
        Bs[lk + 0][lr] = bv.x; Bs[lk + 1][lr] = bv.y;
        Bs[lk + 2][lr] = bv.z; Bs[lk + 3][lr] = bv.w;
        __syncthreads();
#pragma unroll
        for (int kk = 0; kk < 16; kk++) {
            float a[4], b[4];
#pragma unroll
            for (int i = 0; i < 4; i++) a[i] = As[kk][ty + 16 * i];
#pragma unroll
            for (int j = 0; j < 4; j++) b[j] = Bs[kk][tx + 16 * j];
#pragma unroll
            for (int i = 0; i < 4; i++)
#pragma unroll
                for (int j = 0; j < 4; j++)
                    acc[i][j] += a[i] * b[j];
        }
    }

#pragma unroll
    for (int j = 0; j < 4; j++) {
        int n = n0 + tx + 16 * j;
        float bb = 0.0f;
        if (b1) bb += b1[n];
        if (b2) bb += b2[n];
#pragma unroll
        for (int i = 0; i < 4; i++) {
            C[(size_t)(m0 + ty + 16 * i) * N + n] = acc[i][j] + bb;
        }
    }
}

// ---------------- persistent bidirectional LSTM scan ----------------------
// grid = 128 blocks x 256 threads. Blocks 0..63: forward dir, 64..127: backward.
// Each block owns 8 hidden units (=> 32 rows of W_hh, i/f/g/o), weights held in
// registers (64 per thread). Per step: block-local GEMV, gates on threads 0..7,
// publish h via global slot + counter; all 64 blocks of a direction poll the
// counter, then reload the full h vector from L2 (per-step slot => no WAR).
__global__ void __launch_bounds__(256, 1) lstm_scan(
    const float* __restrict__ whf, const float* __restrict__ whb,
    int outid, int cntoff)
{
    const int dir = blockIdx.x >> 6;     // 0 fwd, 1 bwd
    const int blk = blockIdx.x & 63;
    const int tid = threadIdx.x;
    const int row = tid >> 3;            // 0..31 local row
    const int sub = tid & 7;             // 8 threads per row
    const int gate = row >> 3;           // 0..3 = i,f,g,o
    const int unit = row & 7;
    const int grow = gate * HID + blk * 8 + unit;   // global W_hh / z row

    const float* zin = dir ? g_zb : g_zf;
    const float* Whh = dir ? whb : whf;
    float* xout = bufsel(outid);
    unsigned int* mc = g_cnt + cntoff + dir * LSEQ;

    // register-resident W_hh slice: wr[k] = Whh[grow][sub + 8k]
    float wr[64];
#pragma unroll
    for (int k = 0; k < 64; k++) wr[k] = Whh[(size_t)grow * HID + sub + 8 * k];

    __shared__ float hs[HID];
    __shared__ float zs[32];
    hs[tid] = 0.0f; hs[tid + 256] = 0.0f;
    float c = 0.0f;                      // live only on threads 0..7
    __syncthreads();

    for (int t = 0; t < LSEQ; t++) {
        const int ta = dir ? (LSEQ - 1 - t) : t;   // actual time index

        // prefetch input-projection terms for this step (gate threads)
        float z0, z1, z2, z3;
        if (tid < 8) {
            const float* zp = zin + (size_t)ta * G4 + blk * 8 + tid;
            z0 = zp[0];
            z1 = zp[HID];
            z2 = zp[2 * HID];
            z3 = zp[3 * HID];
        }

        // GEMV partial: each thread 64 strided elements (conflict-free LDS)
        float a0 = 0.f, a1 = 0.f, a2 = 0.f, a3 = 0.f;
#pragma unroll
        for (int k = 0; k < 64; k += 4) {
            a0 += wr[k + 0] * hs[sub + 8 * (k + 0)];
            a1 += wr[k + 1] * hs[sub + 8 * (k + 1)];
            a2 += wr[k + 2] * hs[sub + 8 * (k + 2)];
            a3 += wr[k + 3] * hs[sub + 8 * (k + 3)];
        }
        float acc = (a0 + a1) + (a2 + a3);
        // reduce the 8 sub-partials (consecutive lanes)
        acc += __shfl_down_sync(0xffffffffu, acc, 4, 8);
        acc += __shfl_down_sync(0xffffffffu, acc, 2, 8);
        acc += __shfl_down_sync(0xffffffffu, acc, 1, 8);
        if (sub == 0) zs[row] = acc;
        __syncthreads();

        if (tid < 8) {
            float zi = z0 + zs[tid];
            float zf = z1 + zs[8 + tid];
            float zg = z2 + zs[16 + tid];
            float zo = z3 + zs[24 + tid];
            float ig = sigm_f(zi);
            float fg = sigm_f(zf);
            float gg = tanh_f(zg);
            float og = sigm_f(zo);
            c = fg * c + ig * gg;
            float h = og * tanh_f(c);
            // publish h into the output (per-step slot; also the kernel result)
            xout[(size_t)ta * (2 * HID) + dir * HID + blk * 8 + tid] = h;
            __threadfence();
            atomicAdd(mc + t, 1u);
        }

        if (t < LSEQ - 1) {
            if (tid == 0) {
                volatile unsigned int* vp = (volatile unsigned int*)(mc + t);
                while (*vp < 512u) { }
                __threadfence();
            }
            __syncthreads();
            // reload full h_t (L2-fresh via .cg)
            const float2* src =
                (const float2*)(xout + (size_t)ta * (2 * HID) + dir * HID) + tid;
            float2 hv = __ldcg(src);
            hs[2 * tid]     = hv.x;
            hs[2 * tid + 1] = hv.y;
            __syncthreads();
        }
    }
}

// ---------------- pairwise scores ------------------------------------------
// scores[i][j] = sum_m tanh(mlp[i][m] + mlp[j+1][m]) * w[m] + b
// block = 32(i) x 32(j) tile, 256 threads (tx=j lane, ty covers 4 i's), m in
// chunks of 64 staged transposed in smem (conflict-free).
__global__ void __launch_bounds__(256) pair_scores(
    const float* __restrict__ ow, const float* __restrict__ obp,
    float* __restrict__ out)
{
    __shared__ float miT[64][33];
    __shared__ float mjT[64][33];
    __shared__ float wch[64];

    const int tid = threadIdx.x;
    const int tx  = tid & 31;
    const int ty  = tid >> 5;            // 0..7
    const int i0  = blockIdx.y * 32;
    const int j0  = blockIdx.x * 32;

    float acc[4] = {0.f, 0.f, 0.f, 0.f};

    for (int mc = 0; mc < MDIM; mc += 64) {
        __syncthreads();
#pragma unroll
        for (int rep = 0; rep < 8; rep++) {
            int idx  = tid + rep * 256;
            int r    = idx >> 6;          // 0..31
            int cidx = idx & 63;
            miT[cidx][r] = g_mlp[(size_t)(i0 + r) * MDIM + mc + cidx];
            int jrow = j0 + r + 1;
            mjT[cidx][r] = (jrow < LSEQ)
                         ? g_mlp[(size_t)jrow * MDIM + mc + cidx] : 0.0f;
        }
        if (tid < 64) wch[tid] = ow[mc + tid];
        __syncthreads();

#pragma unroll 4
        for (int cc = 0; cc < 64; cc++) {
            float jv = mjT[cc][tx];
            float wv = wch[cc];
#pragma unroll
            for (int ii = 0; ii < 4; ii++) {
                float v = miT[cc][ty + 8 * ii] + jv;
                acc[ii] += tanh_f(v) * wv;
            }
        }
    }

    float ob = obp[0];
    int j = j0 + tx;
    if (j < LSEQ - 1) {
#pragma unroll
        for (int ii = 0; ii < 4; ii++) {
            int i = i0 + ty + 8 * ii;
            out[(size_t)i * (LSEQ - 1) + j] = acc[ii] + ob;
        }
    }
}

// ---------------- launch ----------------------------------------------------
extern "C" void kernel_launch(void* const* d_in, const int* in_sizes, int n_in,
                              void* d_out, int out_size)
{
    const int*   wi    = (const int*)  d_in[0];
    const int*   pi    = (const int*)  d_in[1];
    const float* we    = (const float*)d_in[2];
    const float* pe    = (const float*)d_in[3];
    const float* Wih0  = (const float*)d_in[4];
    const float* Whh0  = (const float*)d_in[5];
    const float* bih0  = (const float*)d_in[6];
    const float* bhh0  = (const float*)d_in[7];
    const float* Wih0r = (const float*)d_in[8];
    const float* Whh0r = (const float*)d_in[9];
    const float* bih0r = (const float*)d_in[10];
    const float* bhh0r = (const float*)d_in[11];
    const float* Wih1  = (const float*)d_in[12];
    const float* Whh1  = (const float*)d_in[13];
    const float* bih1  = (const float*)d_in[14];
    const float* bhh1  = (const float*)d_in[15];
    const float* Wih1r = (const float*)d_in[16];
    const float* Whh1r = (const float*)d_in[17];
    const float* bih1r = (const float*)d_in[18];
    const float* bhh1r = (const float*)d_in[19];
    const float* mlpW  = (const float*)d_in[20];
    const float* mlpb  = (const float*)d_in[21];
    const float* outw  = (const float*)d_in[22];
    const float* outb  = (const float*)d_in[23];

    // embeddings + reset publish counters
    embed_k<<<LSEQ, DIN>>>(wi, pi, we, pe);
    zero_k<<<2, 1024>>>();

    dim3 gz(G4 / 64, LSEQ / 64);       // 32 x 8
    // layer 0 input projections (+ folded biases)
    gemm_tn<<<gz, 256>>>(0, Wih0,  bih0,  bhh0,  3, LSEQ, G4, DIN);
    gemm_tn<<<gz, 256>>>(0, Wih0r, bih0r, bhh0r, 4, LSEQ, G4, DIN);
    // layer 0 bidirectional scan -> g_x1
    lstm_scan<<<128, 256>>>(Whh0, Whh0r, 1, 0);

    // layer 1 input projections
    gemm_tn<<<gz, 256>>>(1, Wih1,  bih1,  bhh1,  3, LSEQ, G4, 2 * HID);
    gemm_tn<<<gz, 256>>>(1, Wih1r, bih1r, bhh1r, 4, LSEQ, G4, 2 * HID);
    // layer 1 bidirectional scan -> g_x2
    lstm_scan<<<128, 256>>>(Whh1, Whh1r, 2, 1024);

    // MLP projection
    gemm_tn<<<dim3(MDIM / 64, LSEQ / 64), 256>>>(2, mlpW, mlpb, nullptr, 5,
                                                 LSEQ, MDIM, 2 * HID);
    // pairwise scores
    pair_scores<<<dim3(16, 16), 256>>>(outw, outb, (float*)d_out);
}

// round 2
// speedup vs baseline: 1.0706x; 1.0706x over previous
#include <cuda_runtime.h>
#include <cuda_bf16.h>

// Problem dims (fixed by the dataset)
#define LSEQ 512
#define DIN  320
#define HID  512
#define G4   2048   // 4*H
#define MDIM 512

// ---------------- scratch (static device globals; no allocation) ----------
__device__ float g_x0 [LSEQ * DIN];        // embeddings
__device__ float g_x1 [LSEQ * 2 * HID];    // layer0 output (fwd cols 0..511, bwd 512..1023)
__device__ float g_x2 [LSEQ * 2 * HID];    // layer1 output
__device__ float g_zf [LSEQ * G4];         // input-projection, forward dir
__device__ float g_zb [LSEQ * G4];         // input-projection, backward dir
__device__ float g_mlp[LSEQ * MDIM];       // per-node MLP
__device__ unsigned int g_cnt[2 * LSEQ];   // per-step publish counters

__device__ __forceinline__ float* bufsel(int id) {
    switch (id) {
        case 0: return g_x0;
        case 1: return g_x1;
        case 2: return g_x2;
        case 3: return g_zf;
        case 4: return g_zb;
        default: return g_mlp;
    }
}

__device__ __forceinline__ float sigm_f(float x) {
    float e = __expf(-x);
    return 1.0f / (1.0f + e);
}
__device__ __forceinline__ float tanh_f(float x) {
    float a = fabsf(x);
    float e = __expf(-2.0f * a);
    float r = (1.0f - e) / (1.0f + e);
    return copysignf(r, x);
}

// release-add (no explicit MEMBAR) / acquire-load for the scan handshake
__device__ __forceinline__ void red_release_add(unsigned int* p, unsigned int v) {
    asm volatile("red.release.gpu.global.add.u32 [%0], %1;" :: "l"(p), "r"(v) : "memory");
}
__device__ __forceinline__ unsigned int ld_acquire_u32(const unsigned int* p) {
    unsigned int v;
    asm volatile("ld.acquire.gpu.global.u32 %0, [%1];" : "=r"(v) : "l"(p) : "memory");
    return v;
}

// ---------------- embedding gather ----------------------------------------
__global__ void embed_k(const int* __restrict__ wi, const int* __restrict__ pi,
                        const float* __restrict__ we, const float* __restrict__ pe)
{
    int t = blockIdx.x;
    int d = threadIdx.x;             // 320 threads
    float v;
    if (d < 256) v = we[(size_t)wi[t] * 256 + d];
    else         v = pe[(size_t)pi[t] * 64 + (d - 256)];
    g_x0[t * DIN + d] = v;
}

// ---------------- counter reset (needed every replay) ---------------------
__global__ void zero_k()
{
    g_cnt[blockIdx.x * 1024 + threadIdx.x] = 0u;
}

// ---------------- f32 GEMM:  C[M,N] = A[M,K] * B[N,K]^T + b1 + b2 ---------
// 64x64 tile, 256 threads, 4x4/thread, K-tile 16. gridDim.z selects the
// (B, bias, C) set so paired direction GEMMs share one launch.
__global__ void __launch_bounds__(256) gemm_tn(
    int aid,
    const float* __restrict__ B0, const float* __restrict__ b1_0,
    const float* __restrict__ b2_0, int cid0,
    const float* __restrict__ B1, const float* __restrict__ b1_1,
    const float* __restrict__ b2_1, int cid1,
    int M, int N, int K)
{
    const float* A  = bufsel(aid);
    const float* B  = blockIdx.z ? B1   : B0;
    const float* b1 = blockIdx.z ? b1_1 : b1_0;
    const float* b2 = blockIdx.z ? b2_1 : b2_0;
    float*       C  = bufsel(blockIdx.z ? cid1 : cid0);

    __shared__ float As[16][65];
    __shared__ float Bs[16][65];

    const int tid = threadIdx.x;
    const int tx  = tid & 15;
    const int ty  = tid >> 4;
    const int m0  = blockIdx.y * 64;
    const int n0  = blockIdx.x * 64;

    const int lr = tid >> 2;         // 0..63 : tile row
    const int lk = (tid & 3) * 4;    // 0,4,8,12 : k offset (float4)

    const float* Ap = A + (size_t)(m0 + lr) * K + lk;
    const float* Bp = B + (size_t)(n0 + lr) * K + lk;

    float acc[4][4] = {};

    for (int k0 = 0; k0 < K; k0 += 16) {
        float4 av = *(const float4*)(Ap + k0);
        float4 bv = *(const float4*)(Bp + k0);
        __syncthreads();
        As[lk + 0][lr] = av.x; As[lk + 1][lr] = av.y;
        As[lk + 2][lr] = av.z; As[lk + 3][lr] = av.w;
        Bs[lk + 0][lr] = bv.x; Bs[lk + 1][lr] = bv.y;
        Bs[lk + 2][lr] = bv.z; Bs[lk + 3][lr] = bv.w;
        __syncthreads();
#pragma unroll
        for (int kk = 0; kk < 16; kk++) {
            float a[4], b[4];
#pragma unroll
            for (int i = 0; i < 4; i++) a[i] = As[kk][ty + 16 * i];
#pragma unroll
            for (int j = 0; j < 4; j++) b[j] = Bs[kk][tx + 16 * j];
#pragma unroll
            for (int i = 0; i < 4; i++)
#pragma unroll
                for (int j = 0; j < 4; j++)
                    acc[i][j] += a[i] * b[j];
        }
    }

#pragma unroll
    for (int j = 0; j < 4; j++) {
        int n = n0 + tx + 16 * j;
        float bb = 0.0f;
        if (b1) bb += b1[n];
        if (b2) bb += b2[n];
#pragma unroll
        for (int i = 0; i < 4; i++) {
            C[(size_t)(m0 + ty + 16 * i) * N + n] = acc[i][j] + bb;
        }
    }
}

// ---------------- persistent bidirectional LSTM scan ----------------------
// 128 blocks x 256 threads; blocks 0..63 fwd, 64..127 bwd. Each block owns 8
// hidden units (32 W_hh rows register-resident as float2 pairs).
// Handshake: threads 0..7 store h, syncwarp, thread0 red.release (+1);
// consumers ld.acquire-poll to 64, then __ldcg-reload h.
__global__ void __launch_bounds__(256, 1) lstm_scan(
    const float* __restrict__ whf, const float* __restrict__ whb,
    int outid, int cntoff)
{
    const int dir = blockIdx.x >> 6;     // 0 fwd, 1 bwd
    const int blk = blockIdx.x & 63;
    const int tid = threadIdx.x;
    const int row = tid >> 3;            // 0..31 local row
    const int sub = tid & 7;             // 8 threads per row
    const int gate = row >> 3;           // 0..3 = i,f,g,o
    const int unit = row & 7;
    const int grow = gate * HID + blk * 8 + unit;   // global W_hh / z row

    const float* zin = dir ? g_zb : g_zf;
    const float* Whh = dir ? whb : whf;
    float* xout = bufsel(outid);
    unsigned int* mc = g_cnt + cntoff + dir * LSEQ;

    // register-resident W_hh slice as float2: covers h[2*(sub+8k)], h[..+1]
    float wrA[32], wrB[32];
    const float2* w2 = (const float2*)(Whh + (size_t)grow * HID);
#pragma unroll
    for (int k = 0; k < 32; k++) {
        float2 wv = w2[sub + 8 * k];
        wrA[k] = wv.x; wrB[k] = wv.y;
    }

    __shared__ float2 hs2[HID / 2];      // 256 float2 = 512 floats
    __shared__ float zs[32];
    hs2[tid] = make_float2(0.0f, 0.0f);
    float c = 0.0f;                      // live only on threads 0..7
    __syncthreads();

    for (int t = 0; t < LSEQ; t++) {
        const int ta = dir ? (LSEQ - 1 - t) : t;   // actual time index

        // prefetch input-projection terms for this step (gate threads)
        float z0, z1, z2, z3;
        if (tid < 8) {
            const float* zp = zin + (size_t)ta * G4 + blk * 8 + tid;
            z0 = zp[0];
            z1 = zp[HID];
            z2 = zp[2 * HID];
            z3 = zp[3 * HID];
        }

        // GEMV partial: 32 x LDS.64 + 64 FMA per thread, conflict-light
        float a0 = 0.f, a1 = 0.f;
#pragma unroll
        for (int k = 0; k < 32; k += 2) {
            float2 h0 = hs2[sub + 8 * k];
            float2 h1 = hs2[sub + 8 * (k + 1)];
            a0 += wrA[k] * h0.x + wrB[k] * h0.y;
            a1 += wrA[k + 1] * h1.x + wrB[k + 1] * h1.y;
        }
        float acc = a0 + a1;
        acc += __shfl_down_sync(0xffffffffu, acc, 4, 8);
        acc += __shfl_down_sync(0xffffffffu, acc, 2, 8);
        acc += __shfl_down_sync(0xffffffffu, acc, 1, 8);
        if (sub == 0) zs[row] = acc;
        __syncthreads();

        if (tid < 8) {
            float zi = z0 + zs[tid];
            float zf = z1 + zs[8 + tid];
            float zg = z2 + zs[16 + tid];
            float zo = z3 + zs[24 + tid];
            float ig = sigm_f(zi);
            float fg = sigm_f(zf);
            float gg = tanh_f(zg);
            float og = sigm_f(zo);
            c = fg * c + ig * gg;
            float h = og * tanh_f(c);
            xout[(size_t)ta * (2 * HID) + dir * HID + blk * 8 + tid] = h;
            __syncwarp(0x000000ffu);
            if (tid == 0 && t < LSEQ - 1)
                red_release_add(mc + t, 1u);   // one arrival per block
        }

        if (t < LSEQ - 1) {
            if (tid == 0) {
                while (ld_acquire_u32(mc + t) < 64u) { }
            }
            __syncthreads();
            // reload full h_t (L2-fresh via .cg)
            const float2* src =
                (const float2*)(xout + (size_t)ta * (2 * HID) + dir * HID) + tid;
            hs2[tid] = __ldcg(src);
            __syncthreads();
        }
    }
}

// ---------------- pairwise scores ------------------------------------------
__global__ void __launch_bounds__(256) pair_scores(
    const float* __restrict__ ow, const float* __restrict__ obp,
    float* __restrict__ out)
{
    __shared__ float miT[64][33];
    __shared__ float mjT[64][33];
    __shared__ float wch[64];

    const int tid = threadIdx.x;
    const int tx  = tid & 31;
    const int ty  = tid >> 5;            // 0..7
    const int i0  = blockIdx.y * 32;
    const int j0  = blockIdx.x * 32;

    float acc[4] = {0.f, 0.f, 0.f, 0.f};

    for (int mc = 0; mc < MDIM; mc += 64) {
        __syncthreads();
#pragma unroll
        for (int rep = 0; rep < 8; rep++) {
            int idx  = tid + rep * 256;
            int r    = idx >> 6;          // 0..31
            int cidx = idx & 63;
            miT[cidx][r] = g_mlp[(size_t)(i0 + r) * MDIM + mc + cidx];
            int jrow = j0 + r + 1;
            mjT[cidx][r] = (jrow < LSEQ)
                         ? g_mlp[(size_t)jrow * MDIM + mc + cidx] : 0.0f;
        }
        if (tid < 64) wch[tid] = ow[mc + tid];
        __syncthreads();

#pragma unroll 4
        for (int cc = 0; cc < 64; cc++) {
            float jv = mjT[cc][tx];
            float wv = wch[cc];
#pragma unroll
            for (int ii = 0; ii < 4; ii++) {
                float v = miT[cc][ty + 8 * ii] + jv;
                acc[ii] += tanh_f(v) * wv;
            }
        }
    }

    float ob = obp[0];
    int j = j0 + tx;
    if (j < LSEQ - 1) {
#pragma unroll
        for (int ii = 0; ii < 4; ii++) {
            int i = i0 + ty + 8 * ii;
            out[(size_t)i * (LSEQ - 1) + j] = acc[ii] + ob;
        }
    }
}

// ---------------- launch ----------------------------------------------------
extern "C" void kernel_launch(void* const* d_in, const int* in_sizes, int n_in,
                              void* d_out, int out_size)
{
    const int*   wi    = (const int*)  d_in[0];
    const int*   pi    = (const int*)  d_in[1];
    const float* we    = (const float*)d_in[2];
    const float* pe    = (const float*)d_in[3];
    const float* Wih0  = (const float*)d_in[4];
    const float* Whh0  = (const float*)d_in[5];
    const float* bih0  = (const float*)d_in[6];
    const float* bhh0  = (const float*)d_in[7];
    const float* Wih0r = (const float*)d_in[8];
    const float* Whh0r = (const float*)d_in[9];
    const float* bih0r = (const float*)d_in[10];
    const float* bhh0r = (const float*)d_in[11];
    const float* Wih1  = (const float*)d_in[12];
    const float* Whh1  = (const float*)d_in[13];
    const float* bih1  = (const float*)d_in[14];
    const float* bhh1  = (const float*)d_in[15];
    const float* Wih1r = (const float*)d_in[16];
    const float* Whh1r = (const float*)d_in[17];
    const float* bih1r = (const float*)d_in[18];
    const float* bhh1r = (const float*)d_in[19];
    const float* mlpW  = (const float*)d_in[20];
    const float* mlpb  = (const float*)d_in[21];
    const float* outw  = (const float*)d_in[22];
    const float* outb  = (const float*)d_in[23];

    embed_k<<<LSEQ, DIN>>>(wi, pi, we, pe);
    zero_k<<<2, 1024>>>();

    // layer 0 input projections (both directions, one launch)
    gemm_tn<<<dim3(G4 / 64, LSEQ / 64, 2), 256>>>(
        0, Wih0, bih0, bhh0, 3, Wih0r, bih0r, bhh0r, 4, LSEQ, G4, DIN);
    // layer 0 bidirectional scan -> g_x1
    lstm_scan<<<128, 256>>>(Whh0, Whh0r, 1, 0);

    // layer 1 input projections
    gemm_tn<<<dim3(G4 / 64, LSEQ / 64, 2), 256>>>(
        1, Wih1, bih1, bhh1, 3, Wih1r, bih1r, bhh1r, 4, LSEQ, G4, 2 * HID);
    // layer 1 bidirectional scan -> g_x2
    lstm_scan<<<128, 256>>>(Whh1, Whh1r, 2, 1024);

    // MLP projection
    gemm_tn<<<dim3(MDIM / 64, LSEQ / 64, 1), 256>>>(
        2, mlpW, mlpb, nullptr, 5, mlpW, mlpb, nullptr, 5, LSEQ, MDIM, 2 * HID);
    // pairwise scores
    pair_scores<<<dim3(16, 16), 256>>>(outw, outb, (float*)d_out);
}